// round 2
// baseline (speedup 1.0000x reference)
#include <cuda_runtime.h>
#include <math.h>
#include <stdint.h>

#define T16        16
#define EMBED      4096
#define NKV        8
#define HD         128
#define CACHE_LEN  32000
#define VALID_LEN  32016          // CACHE + T16
#define NSLICE     32
#define SLICE_LEN  1024
#define NEGB       (-10000.0f)

// output packing in d_out (fp32 elements)
#define OUT_K_OFF  65536          // 16*4096
#define OUT_V_OFF  81920          // 65536 + 8*16*128

// ---------------- scratch (device globals; no allocations allowed) ----------
__device__ float g_h[T16 * EMBED];                     // rmsnorm output
__device__ float g_q[T16 * EMBED];                     // raw q (pre-rope)
__device__ float g_k[T16 * NKV * HD];                  // raw k
__device__ float g_v[T16 * NKV * HD];                  // raw v
__device__ float g_qr[NKV * 64 * HD];                  // roped q, [kv][g*16+t][d]
__device__ float g_sk[NKV * T16 * HD];                 // scaled_k [kv][t][d]
__device__ float g_sv[NKV * T16 * HD];                 // scaled_v [kv][t][d]
__device__ float g_opart[NKV * NSLICE * 64 * HD];      // unnormalized O partials
__device__ float g_mpart[NKV * NSLICE * 64];
__device__ float g_lpart[NKV * NSLICE * 64];
__device__ float g_o[T16 * EMBED];                     // attention output, [t][head*128+d]

// ---------------- 1. RMSNorm ------------------------------------------------
__global__ void rmsnorm_kernel(const float* __restrict__ x,
                               const float* __restrict__ w) {
    int t = blockIdx.x;
    int tid = threadIdx.x;
    __shared__ float red[8];
    __shared__ float s_r;
    float ss = 0.f;
    for (int e = tid; e < EMBED; e += 256) {
        float v = x[t * EMBED + e];
        ss += v * v;
    }
    #pragma unroll
    for (int off = 16; off; off >>= 1) ss += __shfl_xor_sync(0xffffffffu, ss, off);
    if ((tid & 31) == 0) red[tid >> 5] = ss;
    __syncthreads();
    if (tid == 0) {
        float tot = 0.f;
        #pragma unroll
        for (int i = 0; i < 8; i++) tot += red[i];
        s_r = rsqrtf(tot / (float)EMBED + 1e-6f);
    }
    __syncthreads();
    float r = s_r;
    for (int e = tid; e < EMBED; e += 256)
        g_h[t * EMBED + e] = x[t * EMBED + e] * r * w[e];
}

// ---------------- 2. skinny GEMM: Y[t][i] = sum_e X[t][e] * W[i][e] ---------
// mode 0: X=g_h -> g_q ; 1: g_h -> g_k ; 2: g_h -> g_v ; 3: g_o -> Yext
__global__ void __launch_bounds__(256) gemm16_kernel(const float* __restrict__ W,
                                                     int nrows, int mode,
                                                     float* __restrict__ Yext) {
    const float* __restrict__ X = (mode == 3) ? g_o : g_h;
    float* Y;
    if (mode == 0) Y = g_q;
    else if (mode == 1) Y = g_k;
    else if (mode == 2) Y = g_v;
    else Y = Yext;

    int warp = blockIdx.x * 8 + (threadIdx.x >> 5);
    int lane = threadIdx.x & 31;
    if (warp >= nrows) return;
    const float* __restrict__ wrow = W + (size_t)warp * EMBED;

    float acc[T16];
    #pragma unroll
    for (int t = 0; t < T16; t++) acc[t] = 0.f;

    for (int e = lane * 4; e < EMBED; e += 128) {
        float4 w4 = *(const float4*)(wrow + e);
        #pragma unroll
        for (int t = 0; t < T16; t++) {
            float4 x4 = *(const float4*)(X + t * EMBED + e);
            acc[t] += w4.x * x4.x + w4.y * x4.y + w4.z * x4.z + w4.w * x4.w;
        }
    }
    #pragma unroll
    for (int t = 0; t < T16; t++) {
        #pragma unroll
        for (int off = 16; off; off >>= 1)
            acc[t] += __shfl_xor_sync(0xffffffffu, acc[t], off);
    }
    if (lane < T16) Y[lane * nrows + warp] = acc[lane];
}

// ---------------- 3. RoPE + scaled_k/scaled_v -------------------------------
// grid: (48 heads, 16 t), 64 threads (rope pair index j)
__global__ void rope_kernel(const float* __restrict__ cosb,
                            const float* __restrict__ sinb,
                            const float* __restrict__ kq,
                            float* __restrict__ out) {
    int h = blockIdx.x;
    int t = blockIdx.y;
    int j = threadIdx.x;       // 0..63
    float c = cosb[t * 64 + j];
    float s = sinb[t * 64 + j];
    if (h < 32) {                                   // q heads
        const float* u = g_q + t * EMBED + h * HD;
        float x0 = u[j], x1 = u[j + 64];
        int kv = h >> 2, g = h & 3;
        float* dst = g_qr + ((size_t)kv * 64 + g * 16 + t) * HD;
        dst[j]      = x0 * c - x1 * s;
        dst[j + 64] = x0 * s + x1 * c;
    } else if (h < 40) {                            // k heads
        int kh = h - 32;
        const float* u = g_k + t * (NKV * HD) + kh * HD;
        float x0 = u[j], x1 = u[j + 64];
        float sc = kq[0];
        float o0 = (x0 * c - x1 * s) * sc;
        float o1 = (x0 * s + x1 * c) * sc;
        int idx = (kh * T16 + t) * HD;
        g_sk[idx + j] = o0;      g_sk[idx + j + 64] = o1;
        out[OUT_K_OFF + idx + j] = o0;  out[OUT_K_OFF + idx + j + 64] = o1;
    } else {                                        // v heads
        int vh = h - 40;
        const float* u = g_v + t * (NKV * HD) + vh * HD;
        float o0 = fmaxf(u[j],      NEGB);
        float o1 = fmaxf(u[j + 64], NEGB);
        int idx = (vh * T16 + t) * HD;
        g_sv[idx + j] = o0;      g_sv[idx + j + 64] = o1;
        out[OUT_V_OFF + idx + j] = o0;  out[OUT_V_OFF + idx + j + 64] = o1;
    }
}

// ---------------- 4. flash attention, split over context --------------------
// grid (NKV, NSLICE), 256 threads (8 warps). Warp w owns query rows 8w..8w+7
// (row m = g*16+t). Lane owns score cols {2*lane, 2*lane+1} and O dims 4*lane..+3.
extern __shared__ float sm_attn[];

__global__ void __launch_bounds__(256) attn_kernel(const float* __restrict__ KT,
                                                   const float* __restrict__ VC) {
    const int kv    = blockIdx.x;
    const int slice = blockIdx.y;
    const int tid   = threadIdx.x;
    const int lane  = tid & 31;
    const int wid   = tid >> 5;
    const int rm    = wid * 8;

    float* q_s  = sm_attn;              // [64][128]
    float* kt_s = sm_attn + 8192;       // [128][64]
    float* v_s  = sm_attn + 16384;      // [64][128]
    float* p_s  = sm_attn + 24576;      // [64][64]

    const float* qsrc = g_qr + (size_t)kv * 64 * HD;
    for (int i = tid; i < 64 * HD; i += 256) q_s[i] = qsrc[i];

    float m_run[8], l_run[8], o_acc[8][4];
    #pragma unroll
    for (int r = 0; r < 8; r++) {
        m_run[r] = -1e30f; l_run[r] = 0.f;
        o_acc[r][0] = o_acc[r][1] = o_acc[r][2] = o_acc[r][3] = 0.f;
    }

    const int c_begin = slice * SLICE_LEN;
    const int c_end   = min(c_begin + SLICE_LEN, VALID_LEN);
    const int cpair   = 2 * lane;
    const int dbase   = 4 * lane;

    for (int c0 = c_begin; c0 < c_end; c0 += 64) {
        __syncthreads();   // previous tile fully consumed
        // load K^T tile [d][c]  (coalesced: consecutive tid -> consecutive col)
        for (int i = tid; i < 128 * 64; i += 256) {
            int d = i >> 6, cc = i & 63, col = c0 + cc;
            float val = 0.f;
            if (col < CACHE_LEN)
                val = KT[((size_t)kv * HD + d) * CACHE_LEN + col];
            else if (col < VALID_LEN)
                val = g_sk[(kv * T16 + (col - CACHE_LEN)) * HD + d];
            kt_s[i] = val;
        }
        // load V tile [c][d]
        for (int i = tid; i < 64 * 128; i += 256) {
            int cc = i >> 7, d = i & 127, col = c0 + cc;
            float val = 0.f;
            if (col < CACHE_LEN)
                val = VC[((size_t)kv * CACHE_LEN + col) * HD + d];
            else if (col < VALID_LEN)
                val = g_sv[(kv * T16 + (col - CACHE_LEN)) * HD + d];
            v_s[i] = val;
        }
        __syncthreads();

        // ---- QK: s[r][0/1] for cols (c0+2*lane, +1) ----
        float s0[8], s1[8];
        #pragma unroll
        for (int r = 0; r < 8; r++) { s0[r] = 0.f; s1[r] = 0.f; }

        #pragma unroll 2
        for (int d0 = 0; d0 < 128; d0 += 4) {
            float2 k0 = *(const float2*)&kt_s[(d0 + 0) * 64 + cpair];
            float2 k1 = *(const float2*)&kt_s[(d0 + 1) * 64 + cpair];
            float2 k2 = *(const float2*)&kt_s[(d0 + 2) * 64 + cpair];
            float2 k3 = *(const float2*)&kt_s[(d0 + 3) * 64 + cpair];
            #pragma unroll
            for (int r = 0; r < 8; r++) {
                float4 q = *(const float4*)&q_s[(rm + r) * 128 + d0];
                s0[r] += q.x * k0.x + q.y * k1.x + q.z * k2.x + q.w * k3.x;
                s1[r] += q.x * k0.y + q.y * k1.y + q.z * k2.y + q.w * k3.y;
            }
        }

        // ---- mask + online softmax (per warp over its 8 rows) ----
        int col0 = c0 + cpair, col1 = col0 + 1;
        #pragma unroll
        for (int r = 0; r < 8; r++) {
            int m = rm + r;
            int t = m & 15;
            float a = s0[r], b = s1[r];
            if (col0 >= VALID_LEN) a = -1e30f;
            else if (col0 >= CACHE_LEN && (col0 - CACHE_LEN) > t) a += NEGB;
            if (col1 >= VALID_LEN) b = -1e30f;
            else if (col1 >= CACHE_LEN && (col1 - CACHE_LEN) > t) b += NEGB;

            float mx = fmaxf(a, b);
            #pragma unroll
            for (int off = 16; off; off >>= 1)
                mx = fmaxf(mx, __shfl_xor_sync(0xffffffffu, mx, off));
            float mn    = fmaxf(m_run[r], mx);
            float alpha = __expf(m_run[r] - mn);
            float p0 = __expf(a - mn);
            float p1 = __expf(b - mn);
            float ps = p0 + p1;
            #pragma unroll
            for (int off = 16; off; off >>= 1)
                ps += __shfl_xor_sync(0xffffffffu, ps, off);
            l_run[r] = l_run[r] * alpha + ps;
            m_run[r] = mn;
            o_acc[r][0] *= alpha; o_acc[r][1] *= alpha;
            o_acc[r][2] *= alpha; o_acc[r][3] *= alpha;
            *(float2*)&p_s[m * 64 + cpair] = make_float2(p0, p1);
        }
        __syncwarp();

        // ---- PV: O[r][dbase..+3] += sum_c p[r][c] * v[c][d] ----
        #pragma unroll 4
        for (int cc = 0; cc < 64; cc += 2) {
            float4 v0 = *(const float4*)&v_s[(cc + 0) * 128 + dbase];
            float4 v1 = *(const float4*)&v_s[(cc + 1) * 128 + dbase];
            #pragma unroll
            for (int r = 0; r < 8; r++) {
                float2 p = *(const float2*)&p_s[(rm + r) * 64 + cc];
                o_acc[r][0] += p.x * v0.x + p.y * v1.x;
                o_acc[r][1] += p.x * v0.y + p.y * v1.y;
                o_acc[r][2] += p.x * v0.z + p.y * v1.z;
                o_acc[r][3] += p.x * v0.w + p.y * v1.w;
            }
        }
    }

    // ---- write partials (unnormalized O, running m, l) ----
    size_t pb = (size_t)(kv * NSLICE + slice) * 64;
    #pragma unroll
    for (int r = 0; r < 8; r++) {
        *(float4*)&g_opart[(pb + rm + r) * HD + dbase] =
            make_float4(o_acc[r][0], o_acc[r][1], o_acc[r][2], o_acc[r][3]);
    }
    if (lane == 0) {
        #pragma unroll
        for (int r = 0; r < 8; r++) {
            g_mpart[pb + rm + r] = m_run[r];
            g_lpart[pb + rm + r] = l_run[r];
        }
    }
}

// ---------------- 5. combine split-context partials -------------------------
// grid 512 blocks = (kv, m); 128 threads = d
__global__ void __launch_bounds__(128) combine_kernel() {
    int b  = blockIdx.x;
    int kv = b >> 6;
    int m  = b & 63;
    int d  = threadIdx.x;
    size_t base = (size_t)kv * NSLICE * 64 + m;

    float M = -1e30f;
    #pragma unroll
    for (int s = 0; s < NSLICE; s++)
        M = fmaxf(M, g_mpart[base + s * 64]);
    float num = 0.f, den = 0.f;
    #pragma unroll 4
    for (int s = 0; s < NSLICE; s++) {
        float w = __expf(g_mpart[base + s * 64] - M);
        den += w * g_lpart[base + s * 64];
        num += w * g_opart[(base + s * 64) * HD + d];
    }
    int g = m >> 4, t = m & 15;
    g_o[t * EMBED + (kv * 4 + g) * HD + d] = num / den;
}

// ---------------- launch -----------------------------------------------------
extern "C" void kernel_launch(void* const* d_in, const int* in_sizes, int n_in,
                              void* d_out, int out_size) {
    const float* x      = (const float*)d_in[0];
    const float* norm_w = (const float*)d_in[1];
    const float* wq     = (const float*)d_in[2];
    const float* wk     = (const float*)d_in[3];
    const float* wv     = (const float*)d_in[4];
    const float* wo     = (const float*)d_in[5];
    const float* rc     = (const float*)d_in[6];
    const float* rs     = (const float*)d_in[7];
    const float* ktc    = (const float*)d_in[8];
    const float* vc     = (const float*)d_in[9];
    // d_in[10] = attn_bias (reproduced analytically)
    const float* kq     = (const float*)d_in[11];
    float* out = (float*)d_out;

    const int ATTN_SMEM = (8192 + 8192 + 8192 + 4096) * 4;   // 114688 B
    cudaFuncSetAttribute(attn_kernel,
                         cudaFuncAttributeMaxDynamicSharedMemorySize, ATTN_SMEM);

    rmsnorm_kernel<<<16, 256>>>(x, norm_w);
    gemm16_kernel<<<512, 256>>>(wq, 4096, 0, nullptr);
    gemm16_kernel<<<128, 256>>>(wk, 1024, 1, nullptr);
    gemm16_kernel<<<128, 256>>>(wv, 1024, 2, nullptr);
    rope_kernel<<<dim3(48, 16), 64>>>(rc, rs, kq, out);
    attn_kernel<<<dim3(NKV, NSLICE), 256, ATTN_SMEM>>>(ktc, vc);
    combine_kernel<<<512, 128>>>();
    gemm16_kernel<<<512, 256>>>(wo, 4096, 3, out);
}

// round 4
// speedup vs baseline: 1.0758x; 1.0758x over previous
#include <cuda_runtime.h>
#include <math.h>
#include <stdint.h>

#define T16        16
#define EMBED      4096
#define NKV        8
#define HD         128
#define CACHE_LEN  32000
#define VALID_LEN  32016          // CACHE + T16
#define NSLICE     64
#define SLICE_LEN  512
#define NEGB       (-10000.0f)

// output packing in d_out (fp32 elements)
#define OUT_K_OFF  65536          // 16*4096
#define OUT_V_OFF  81920          // 65536 + 8*16*128

// ---------------- scratch (device globals; no allocations allowed) ----------
__device__ float g_h[T16 * EMBED];                     // rmsnorm output
__device__ float g_q[T16 * EMBED];                     // raw q (pre-rope)
__device__ float g_k[T16 * NKV * HD];                  // raw k
__device__ float g_v[T16 * NKV * HD];                  // raw v
__device__ float g_qr[NKV * 64 * HD];                  // roped q, [kv][g*16+t][d]
__device__ float g_sk[NKV * T16 * HD];                 // scaled_k [kv][t][d]
__device__ float g_sv[NKV * T16 * HD];                 // scaled_v [kv][t][d]
__device__ float g_opart[NKV * NSLICE * 64 * HD];      // unnormalized O partials
__device__ float g_mpart[NKV * NSLICE * 64];
__device__ float g_lpart[NKV * NSLICE * 64];
__device__ float g_o[T16 * EMBED];                     // attention output, [t][head*128+d]

// ---------------- 1. RMSNorm ------------------------------------------------
__global__ void rmsnorm_kernel(const float* __restrict__ x,
                               const float* __restrict__ w) {
    int t = blockIdx.x;
    int tid = threadIdx.x;
    __shared__ float red[8];
    __shared__ float s_r;
    float ss = 0.f;
    for (int e = tid; e < EMBED; e += 256) {
        float v = x[t * EMBED + e];
        ss += v * v;
    }
    #pragma unroll
    for (int off = 16; off; off >>= 1) ss += __shfl_xor_sync(0xffffffffu, ss, off);
    if ((tid & 31) == 0) red[tid >> 5] = ss;
    __syncthreads();
    if (tid == 0) {
        float tot = 0.f;
        #pragma unroll
        for (int i = 0; i < 8; i++) tot += red[i];
        s_r = rsqrtf(tot / (float)EMBED + 1e-6f);
    }
    __syncthreads();
    float r = s_r;
    for (int e = tid; e < EMBED; e += 256)
        g_h[t * EMBED + e] = x[t * EMBED + e] * r * w[e];
}

// ---------------- 2. skinny GEMM core: Y[t][i] = sum_e X[t][e] * W[i][e] ----
// Each warp: 2 rows, e-loop unrolled x2 (4 W-loads in flight). Block: 16 rows.
__device__ __forceinline__ void gemm16_rows(const float* __restrict__ W,
                                            const float* __restrict__ X,
                                            float* __restrict__ Y,
                                            int nrows, int row0) {
    int wid  = threadIdx.x >> 5;
    int lane = threadIdx.x & 31;
    int r0 = row0 + wid * 2;
    const float* __restrict__ w0 = W + (size_t)r0 * EMBED;
    const float* __restrict__ w1 = W + (size_t)(r0 + 1) * EMBED;

    float acc0[T16], acc1[T16];
    #pragma unroll
    for (int t = 0; t < T16; t++) { acc0[t] = 0.f; acc1[t] = 0.f; }

    #pragma unroll 1
    for (int eb = 0; eb < EMBED; eb += 256) {
        int e = eb + lane * 4;
        float4 a0 = __ldg((const float4*)(w0 + e));
        float4 a1 = __ldg((const float4*)(w0 + e + 128));
        float4 b0 = __ldg((const float4*)(w1 + e));
        float4 b1 = __ldg((const float4*)(w1 + e + 128));
        #pragma unroll
        for (int t = 0; t < T16; t++) {
            float4 x0 = *(const float4*)(X + t * EMBED + e);
            float4 x1 = *(const float4*)(X + t * EMBED + e + 128);
            acc0[t] += a0.x * x0.x + a0.y * x0.y + a0.z * x0.z + a0.w * x0.w
                     + a1.x * x1.x + a1.y * x1.y + a1.z * x1.z + a1.w * x1.w;
            acc1[t] += b0.x * x0.x + b0.y * x0.y + b0.z * x0.z + b0.w * x0.w
                     + b1.x * x1.x + b1.y * x1.y + b1.z * x1.z + b1.w * x1.w;
        }
    }
    #pragma unroll
    for (int t = 0; t < T16; t++) {
        #pragma unroll
        for (int off = 16; off; off >>= 1) {
            acc0[t] += __shfl_xor_sync(0xffffffffu, acc0[t], off);
            acc1[t] += __shfl_xor_sync(0xffffffffu, acc1[t], off);
        }
    }
    if (lane < T16) {
        Y[lane * nrows + r0]     = acc0[lane];
        Y[lane * nrows + r0 + 1] = acc1[lane];
    }
}

// fused QKV: blocks [0,256) -> wq, [256,320) -> wk, [320,384) -> wv
__global__ void __launch_bounds__(256) qkv_gemm_kernel(const float* __restrict__ Wq,
                                                       const float* __restrict__ Wk,
                                                       const float* __restrict__ Wv) {
    int b = blockIdx.x;
    if (b < 256)      gemm16_rows(Wq, g_h, g_q, 4096, b * 16);
    else if (b < 320) gemm16_rows(Wk, g_h, g_k, 1024, (b - 256) * 16);
    else              gemm16_rows(Wv, g_h, g_v, 1024, (b - 320) * 16);
}

__global__ void __launch_bounds__(256) wo_gemm_kernel(const float* __restrict__ Wo,
                                                      float* __restrict__ out) {
    gemm16_rows(Wo, g_o, out, 4096, blockIdx.x * 16);
}

// ---------------- 3. RoPE + scaled_k/scaled_v -------------------------------
// grid: (48 heads, 16 t), 64 threads (rope pair index j)
__global__ void rope_kernel(const float* __restrict__ cosb,
                            const float* __restrict__ sinb,
                            const float* __restrict__ kq,
                            float* __restrict__ out) {
    int h = blockIdx.x;
    int t = blockIdx.y;
    int j = threadIdx.x;       // 0..63
    float c = cosb[t * 64 + j];
    float s = sinb[t * 64 + j];
    if (h < 32) {                                   // q heads
        const float* u = g_q + t * EMBED + h * HD;
        float x0 = u[j], x1 = u[j + 64];
        int kv = h >> 2, g = h & 3;
        float* dst = g_qr + ((size_t)kv * 64 + g * 16 + t) * HD;
        dst[j]      = x0 * c - x1 * s;
        dst[j + 64] = x0 * s + x1 * c;
    } else if (h < 40) {                            // k heads
        int kh = h - 32;
        const float* u = g_k + t * (NKV * HD) + kh * HD;
        float x0 = u[j], x1 = u[j + 64];
        float sc = kq[0];
        float o0 = (x0 * c - x1 * s) * sc;
        float o1 = (x0 * s + x1 * c) * sc;
        int idx = (kh * T16 + t) * HD;
        g_sk[idx + j] = o0;      g_sk[idx + j + 64] = o1;
        out[OUT_K_OFF + idx + j] = o0;  out[OUT_K_OFF + idx + j + 64] = o1;
    } else {                                        // v heads
        int vh = h - 40;
        const float* u = g_v + t * (NKV * HD) + vh * HD;
        float o0 = fmaxf(u[j],      NEGB);
        float o1 = fmaxf(u[j + 64], NEGB);
        int idx = (vh * T16 + t) * HD;
        g_sv[idx + j] = o0;      g_sv[idx + j + 64] = o1;
        out[OUT_V_OFF + idx + j] = o0;  out[OUT_V_OFF + idx + j + 64] = o1;
    }
}

// ---------------- 4. flash attention, split over context --------------------
// grid (NKV, NSLICE), 256 threads (8 warps). Warp w owns query rows 8w..8w+7
// (row m = g*16+t). Lane owns score cols {2*lane, 2*lane+1} and O dims 4*lane..+3.
extern __shared__ float sm_attn[];

__global__ void __launch_bounds__(256) attn_kernel(const float* __restrict__ KT,
                                                   const float* __restrict__ VC) {
    const int kv    = blockIdx.x;
    const int slice = blockIdx.y;
    const int tid   = threadIdx.x;
    const int lane  = tid & 31;
    const int wid   = tid >> 5;
    const int rm    = wid * 8;

    float* q_s  = sm_attn;              // [64][128]
    float* kt_s = sm_attn + 8192;       // [128][64]
    float* v_s  = sm_attn + 16384;      // [64][128]
    float* p_s  = sm_attn + 24576;      // [64][64]

    const float* qsrc = g_qr + (size_t)kv * 64 * HD;
    for (int i = tid; i < 64 * HD; i += 256) q_s[i] = qsrc[i];

    float m_run[8], l_run[8], o_acc[8][4];
    #pragma unroll
    for (int r = 0; r < 8; r++) {
        m_run[r] = -1e30f; l_run[r] = 0.f;
        o_acc[r][0] = o_acc[r][1] = o_acc[r][2] = o_acc[r][3] = 0.f;
    }

    const int c_begin = slice * SLICE_LEN;
    const int c_end   = min(c_begin + SLICE_LEN, VALID_LEN);
    const int cpair   = 2 * lane;
    const int dbase   = 4 * lane;

    for (int c0 = c_begin; c0 < c_end; c0 += 64) {
        __syncthreads();   // previous tile fully consumed
        // load K^T tile [d][c]  (coalesced: consecutive tid -> consecutive col)
        for (int i = tid; i < 128 * 64; i += 256) {
            int d = i >> 6, cc = i & 63, col = c0 + cc;
            float val = 0.f;
            if (col < CACHE_LEN)
                val = KT[((size_t)kv * HD + d) * CACHE_LEN + col];
            else if (col < VALID_LEN)
                val = g_sk[(kv * T16 + (col - CACHE_LEN)) * HD + d];
            kt_s[i] = val;
        }
        // load V tile [c][d]
        for (int i = tid; i < 64 * 128; i += 256) {
            int cc = i >> 7, d = i & 127, col = c0 + cc;
            float val = 0.f;
            if (col < CACHE_LEN)
                val = VC[((size_t)kv * CACHE_LEN + col) * HD + d];
            else if (col < VALID_LEN)
                val = g_sv[(kv * T16 + (col - CACHE_LEN)) * HD + d];
            v_s[i] = val;
        }
        __syncthreads();

        // ---- QK: s[r][0/1] for cols (c0+2*lane, +1) ----
        float s0[8], s1[8];
        #pragma unroll
        for (int r = 0; r < 8; r++) { s0[r] = 0.f; s1[r] = 0.f; }

        #pragma unroll 2
        for (int d0 = 0; d0 < 128; d0 += 4) {
            float2 k0 = *(const float2*)&kt_s[(d0 + 0) * 64 + cpair];
            float2 k1 = *(const float2*)&kt_s[(d0 + 1) * 64 + cpair];
            float2 k2 = *(const float2*)&kt_s[(d0 + 2) * 64 + cpair];
            float2 k3 = *(const float2*)&kt_s[(d0 + 3) * 64 + cpair];
            #pragma unroll
            for (int r = 0; r < 8; r++) {
                float4 q = *(const float4*)&q_s[(rm + r) * 128 + d0];
                s0[r] += q.x * k0.x + q.y * k1.x + q.z * k2.x + q.w * k3.x;
                s1[r] += q.x * k0.y + q.y * k1.y + q.z * k2.y + q.w * k3.y;
            }
        }

        // ---- mask + online softmax (per warp over its 8 rows) ----
        int col0 = c0 + cpair, col1 = col0 + 1;
        #pragma unroll
        for (int r = 0; r < 8; r++) {
            int m = rm + r;
            int t = m & 15;
            float a = s0[r], b = s1[r];
            if (col0 >= VALID_LEN) a = -1e30f;
            else if (col0 >= CACHE_LEN && (col0 - CACHE_LEN) > t) a += NEGB;
            if (col1 >= VALID_LEN) b = -1e30f;
            else if (col1 >= CACHE_LEN && (col1 - CACHE_LEN) > t) b += NEGB;

            float mx = fmaxf(a, b);
            #pragma unroll
            for (int off = 16; off; off >>= 1)
                mx = fmaxf(mx, __shfl_xor_sync(0xffffffffu, mx, off));
            float mn    = fmaxf(m_run[r], mx);
            float alpha = __expf(m_run[r] - mn);
            float p0 = __expf(a - mn);
            float p1 = __expf(b - mn);
            float ps = p0 + p1;
            #pragma unroll
            for (int off = 16; off; off >>= 1)
                ps += __shfl_xor_sync(0xffffffffu, ps, off);
            l_run[r] = l_run[r] * alpha + ps;
            m_run[r] = mn;
            o_acc[r][0] *= alpha; o_acc[r][1] *= alpha;
            o_acc[r][2] *= alpha; o_acc[r][3] *= alpha;
            *(float2*)&p_s[m * 64 + cpair] = make_float2(p0, p1);
        }
        __syncwarp();

        // ---- PV: O[r][dbase..+3] += sum_c p[r][c] * v[c][d] ----
        #pragma unroll 4
        for (int cc = 0; cc < 64; cc += 2) {
            float4 v0 = *(const float4*)&v_s[(cc + 0) * 128 + dbase];
            float4 v1 = *(const float4*)&v_s[(cc + 1) * 128 + dbase];
            #pragma unroll
            for (int r = 0; r < 8; r++) {
                float2 p = *(const float2*)&p_s[(rm + r) * 64 + cc];
                o_acc[r][0] += p.x * v0.x + p.y * v1.x;
                o_acc[r][1] += p.x * v0.y + p.y * v1.y;
                o_acc[r][2] += p.x * v0.z + p.y * v1.z;
                o_acc[r][3] += p.x * v0.w + p.y * v1.w;
            }
        }
    }

    // ---- write partials (unnormalized O, running m, l) ----
    size_t pb = (size_t)(kv * NSLICE + slice) * 64;
    #pragma unroll
    for (int r = 0; r < 8; r++) {
        *(float4*)&g_opart[(pb + rm + r) * HD + dbase] =
            make_float4(o_acc[r][0], o_acc[r][1], o_acc[r][2], o_acc[r][3]);
    }
    if (lane == 0) {
        #pragma unroll
        for (int r = 0; r < 8; r++) {
            g_mpart[pb + rm + r] = m_run[r];
            g_lpart[pb + rm + r] = l_run[r];
        }
    }
}

// ---------------- 5. combine split-context partials -------------------------
// grid 512 blocks = (kv, m); 128 threads = d
__global__ void __launch_bounds__(128) combine_kernel() {
    int b  = blockIdx.x;
    int kv = b >> 6;
    int m  = b & 63;
    int d  = threadIdx.x;
    size_t base = (size_t)kv * NSLICE * 64 + m;

    float M = -1e30f;
    #pragma unroll
    for (int s = 0; s < NSLICE; s++)
        M = fmaxf(M, g_mpart[base + s * 64]);
    float num = 0.f, den = 0.f;
    #pragma unroll 4
    for (int s = 0; s < NSLICE; s++) {
        float w = __expf(g_mpart[base + s * 64] - M);
        den += w * g_lpart[base + s * 64];
        num += w * g_opart[(base + s * 64) * HD + d];
    }
    int g = m >> 4, t = m & 15;
    g_o[t * EMBED + (kv * 4 + g) * HD + d] = num / den;
}

// ---------------- launch -----------------------------------------------------
extern "C" void kernel_launch(void* const* d_in, const int* in_sizes, int n_in,
                              void* d_out, int out_size) {
    const float* x      = (const float*)d_in[0];
    const float* norm_w = (const float*)d_in[1];
    const float* wq     = (const float*)d_in[2];
    const float* wk     = (const float*)d_in[3];
    const float* wv     = (const float*)d_in[4];
    const float* wo     = (const float*)d_in[5];
    const float* rc     = (const float*)d_in[6];
    const float* rs     = (const float*)d_in[7];
    const float* ktc    = (const float*)d_in[8];
    const float* vc     = (const float*)d_in[9];
    // d_in[10] = attn_bias (reproduced analytically)
    const float* kq     = (const float*)d_in[11];
    float* out = (float*)d_out;

    const int ATTN_SMEM = (8192 + 8192 + 8192 + 4096) * 4;   // 114688 B
    cudaFuncSetAttribute(attn_kernel,
                         cudaFuncAttributeMaxDynamicSharedMemorySize, ATTN_SMEM);

    rmsnorm_kernel<<<16, 256>>>(x, norm_w);
    qkv_gemm_kernel<<<384, 256>>>(wq, wk, wv);
    rope_kernel<<<dim3(48, 16), 64>>>(rc, rs, kq, out);
    attn_kernel<<<dim3(NKV, NSLICE), 256, ATTN_SMEM>>>(ktc, vc);
    combine_kernel<<<512, 128>>>();
    wo_gemm_kernel<<<256, 256>>>(wo, out);
}

// round 5
// speedup vs baseline: 1.0773x; 1.0014x over previous
#include <cuda_runtime.h>
#include <math.h>
#include <stdint.h>

#define T16        16
#define EMBED      4096
#define NKV        8
#define HD         128
#define CACHE_LEN  32000
#define VALID_LEN  32016          // CACHE + T16
#define NSLICE     64
#define SLICE_LEN  512
#define NEGB       (-10000.0f)

// output packing in d_out (fp32 elements)
#define OUT_K_OFF  65536          // 16*4096
#define OUT_V_OFF  81920          // 65536 + 8*16*128

// ---------------- scratch (device globals; no allocations allowed) ----------
__device__ float g_h[T16 * EMBED];                     // rmsnorm output
__device__ float g_q[T16 * EMBED];                     // raw q (pre-rope)
__device__ float g_k[T16 * NKV * HD];                  // raw k
__device__ float g_v[T16 * NKV * HD];                  // raw v
__device__ float g_qr[NKV * 64 * HD];                  // roped q, [kv][g*16+t][d]
__device__ float g_sk[NKV * T16 * HD];                 // scaled_k [kv][t][d]
__device__ float g_sv[NKV * T16 * HD];                 // scaled_v [kv][t][d]
__device__ float g_opart[NKV * NSLICE * 64 * HD];      // unnormalized O partials
__device__ float g_mpart[NKV * NSLICE * 64];
__device__ float g_lpart[NKV * NSLICE * 64];
__device__ float g_o[T16 * EMBED];                     // attention output, [t][head*128+d]

// ---------------- 1. RMSNorm ------------------------------------------------
__global__ void rmsnorm_kernel(const float* __restrict__ x,
                               const float* __restrict__ w) {
    int t = blockIdx.x;
    int tid = threadIdx.x;
    __shared__ float red[8];
    __shared__ float s_r;
    float ss = 0.f;
    for (int e = tid; e < EMBED; e += 256) {
        float v = x[t * EMBED + e];
        ss += v * v;
    }
    #pragma unroll
    for (int off = 16; off; off >>= 1) ss += __shfl_xor_sync(0xffffffffu, ss, off);
    if ((tid & 31) == 0) red[tid >> 5] = ss;
    __syncthreads();
    if (tid == 0) {
        float tot = 0.f;
        #pragma unroll
        for (int i = 0; i < 8; i++) tot += red[i];
        s_r = rsqrtf(tot / (float)EMBED + 1e-6f);
    }
    __syncthreads();
    float r = s_r;
    for (int e = tid; e < EMBED; e += 256)
        g_h[t * EMBED + e] = x[t * EMBED + e] * r * w[e];
}

// ---------------- 2. skinny GEMM core: Y[t][i] = sum_e X[t][e] * W[i][e] ----
// Each warp: 2 rows, e-loop unrolled x2 (4 W-loads in flight). Block: 16 rows.
__device__ __forceinline__ void gemm16_rows(const float* __restrict__ W,
                                            const float* __restrict__ X,
                                            float* __restrict__ Y,
                                            int nrows, int row0) {
    int wid  = threadIdx.x >> 5;
    int lane = threadIdx.x & 31;
    int r0 = row0 + wid * 2;
    const float* __restrict__ w0 = W + (size_t)r0 * EMBED;
    const float* __restrict__ w1 = W + (size_t)(r0 + 1) * EMBED;

    float acc0[T16], acc1[T16];
    #pragma unroll
    for (int t = 0; t < T16; t++) { acc0[t] = 0.f; acc1[t] = 0.f; }

    #pragma unroll 1
    for (int eb = 0; eb < EMBED; eb += 256) {
        int e = eb + lane * 4;
        float4 a0 = __ldg((const float4*)(w0 + e));
        float4 a1 = __ldg((const float4*)(w0 + e + 128));
        float4 b0 = __ldg((const float4*)(w1 + e));
        float4 b1 = __ldg((const float4*)(w1 + e + 128));
        #pragma unroll
        for (int t = 0; t < T16; t++) {
            float4 x0 = *(const float4*)(X + t * EMBED + e);
            float4 x1 = *(const float4*)(X + t * EMBED + e + 128);
            acc0[t] += a0.x * x0.x + a0.y * x0.y + a0.z * x0.z + a0.w * x0.w
                     + a1.x * x1.x + a1.y * x1.y + a1.z * x1.z + a1.w * x1.w;
            acc1[t] += b0.x * x0.x + b0.y * x0.y + b0.z * x0.z + b0.w * x0.w
                     + b1.x * x1.x + b1.y * x1.y + b1.z * x1.z + b1.w * x1.w;
        }
    }
    #pragma unroll
    for (int t = 0; t < T16; t++) {
        #pragma unroll
        for (int off = 16; off; off >>= 1) {
            acc0[t] += __shfl_xor_sync(0xffffffffu, acc0[t], off);
            acc1[t] += __shfl_xor_sync(0xffffffffu, acc1[t], off);
        }
    }
    if (lane < T16) {
        Y[lane * nrows + r0]     = acc0[lane];
        Y[lane * nrows + r0 + 1] = acc1[lane];
    }
}

// fused QKV: blocks [0,256) -> wq, [256,320) -> wk, [320,384) -> wv
__global__ void __launch_bounds__(256) qkv_gemm_kernel(const float* __restrict__ Wq,
                                                       const float* __restrict__ Wk,
                                                       const float* __restrict__ Wv) {
    int b = blockIdx.x;
    if (b < 256)      gemm16_rows(Wq, g_h, g_q, 4096, b * 16);
    else if (b < 320) gemm16_rows(Wk, g_h, g_k, 1024, (b - 256) * 16);
    else              gemm16_rows(Wv, g_h, g_v, 1024, (b - 320) * 16);
}

__global__ void __launch_bounds__(256) wo_gemm_kernel(const float* __restrict__ Wo,
                                                      float* __restrict__ out) {
    gemm16_rows(Wo, g_o, out, 4096, blockIdx.x * 16);
}

// ---------------- 3. RoPE + scaled_k/scaled_v -------------------------------
// grid: (48 heads, 16 t), 64 threads (rope pair index j)
__global__ void rope_kernel(const float* __restrict__ cosb,
                            const float* __restrict__ sinb,
                            const float* __restrict__ kq,
                            float* __restrict__ out) {
    int h = blockIdx.x;
    int t = blockIdx.y;
    int j = threadIdx.x;       // 0..63
    float c = cosb[t * 64 + j];
    float s = sinb[t * 64 + j];
    if (h < 32) {                                   // q heads
        const float* u = g_q + t * EMBED + h * HD;
        float x0 = u[j], x1 = u[j + 64];
        int kv = h >> 2, g = h & 3;
        float* dst = g_qr + ((size_t)kv * 64 + g * 16 + t) * HD;
        dst[j]      = x0 * c - x1 * s;
        dst[j + 64] = x0 * s + x1 * c;
    } else if (h < 40) {                            // k heads
        int kh = h - 32;
        const float* u = g_k + t * (NKV * HD) + kh * HD;
        float x0 = u[j], x1 = u[j + 64];
        float sc = kq[0];
        float o0 = (x0 * c - x1 * s) * sc;
        float o1 = (x0 * s + x1 * c) * sc;
        int idx = (kh * T16 + t) * HD;
        g_sk[idx + j] = o0;      g_sk[idx + j + 64] = o1;
        out[OUT_K_OFF + idx + j] = o0;  out[OUT_K_OFF + idx + j + 64] = o1;
    } else {                                        // v heads
        int vh = h - 40;
        const float* u = g_v + t * (NKV * HD) + vh * HD;
        float o0 = fmaxf(u[j],      NEGB);
        float o1 = fmaxf(u[j + 64], NEGB);
        int idx = (vh * T16 + t) * HD;
        g_sv[idx + j] = o0;      g_sv[idx + j + 64] = o1;
        out[OUT_V_OFF + idx + j] = o0;  out[OUT_V_OFF + idx + j + 64] = o1;
    }
}

// ---------------- 4. flash attention, split over context --------------------
// grid (NKV, NSLICE), 256 threads (8 warps). Warp w owns query rows 8w..8w+7
// (row m = g*16+t). Lane owns score cols {2*lane, 2*lane+1} and O dims 4*lane..+3.
extern __shared__ float sm_attn[];

__global__ void __launch_bounds__(256) attn_kernel(const float* __restrict__ KT,
                                                   const float* __restrict__ VC) {
    const int kv    = blockIdx.x;
    const int slice = blockIdx.y;
    const int tid   = threadIdx.x;
    const int lane  = tid & 31;
    const int wid   = tid >> 5;
    const int rm    = wid * 8;

    float* q_s  = sm_attn;              // [64][128]
    float* kt_s = sm_attn + 8192;       // [128][64]
    float* v_s  = sm_attn + 16384;      // [64][128]
    float* p_s  = sm_attn + 24576;      // [64][64]

    const float* qsrc = g_qr + (size_t)kv * 64 * HD;
    for (int i = tid; i < 64 * HD; i += 256) q_s[i] = qsrc[i];

    float m_run[8], l_run[8], o_acc[8][4];
    #pragma unroll
    for (int r = 0; r < 8; r++) {
        m_run[r] = -1e30f; l_run[r] = 0.f;
        o_acc[r][0] = o_acc[r][1] = o_acc[r][2] = o_acc[r][3] = 0.f;
    }

    const int c_begin = slice * SLICE_LEN;
    const int c_end   = min(c_begin + SLICE_LEN, VALID_LEN);
    const int cpair   = 2 * lane;
    const int dbase   = 4 * lane;

    for (int c0 = c_begin; c0 < c_end; c0 += 64) {
        __syncthreads();   // previous tile fully consumed
        // load K^T tile [d][c]  (coalesced: consecutive tid -> consecutive col)
        for (int i = tid; i < 128 * 64; i += 256) {
            int d = i >> 6, cc = i & 63, col = c0 + cc;
            float val = 0.f;
            if (col < CACHE_LEN)
                val = KT[((size_t)kv * HD + d) * CACHE_LEN + col];
            else if (col < VALID_LEN)
                val = g_sk[(kv * T16 + (col - CACHE_LEN)) * HD + d];
            kt_s[i] = val;
        }
        // load V tile [c][d]
        for (int i = tid; i < 64 * 128; i += 256) {
            int cc = i >> 7, d = i & 127, col = c0 + cc;
            float val = 0.f;
            if (col < CACHE_LEN)
                val = VC[((size_t)kv * CACHE_LEN + col) * HD + d];
            else if (col < VALID_LEN)
                val = g_sv[(kv * T16 + (col - CACHE_LEN)) * HD + d];
            v_s[i] = val;
        }
        __syncthreads();

        // ---- QK: s[r][0/1] for cols (c0+2*lane, +1) ----
        float s0[8], s1[8];
        #pragma unroll
        for (int r = 0; r < 8; r++) { s0[r] = 0.f; s1[r] = 0.f; }

        #pragma unroll 2
        for (int d0 = 0; d0 < 128; d0 += 4) {
            float2 k0 = *(const float2*)&kt_s[(d0 + 0) * 64 + cpair];
            float2 k1 = *(const float2*)&kt_s[(d0 + 1) * 64 + cpair];
            float2 k2 = *(const float2*)&kt_s[(d0 + 2) * 64 + cpair];
            float2 k3 = *(const float2*)&kt_s[(d0 + 3) * 64 + cpair];
            #pragma unroll
            for (int r = 0; r < 8; r++) {
                float4 q = *(const float4*)&q_s[(rm + r) * 128 + d0];
                s0[r] += q.x * k0.x + q.y * k1.x + q.z * k2.x + q.w * k3.x;
                s1[r] += q.x * k0.y + q.y * k1.y + q.z * k2.y + q.w * k3.y;
            }
        }

        // ---- mask + online softmax (per warp over its 8 rows) ----
        int col0 = c0 + cpair, col1 = col0 + 1;
        #pragma unroll
        for (int r = 0; r < 8; r++) {
            int m = rm + r;
            int t = m & 15;
            float a = s0[r], b = s1[r];
            if (col0 >= VALID_LEN) a = -1e30f;
            else if (col0 >= CACHE_LEN && (col0 - CACHE_LEN) > t) a += NEGB;
            if (col1 >= VALID_LEN) b = -1e30f;
            else if (col1 >= CACHE_LEN && (col1 - CACHE_LEN) > t) b += NEGB;

            float mx = fmaxf(a, b);
            #pragma unroll
            for (int off = 16; off; off >>= 1)
                mx = fmaxf(mx, __shfl_xor_sync(0xffffffffu, mx, off));
            float mn    = fmaxf(m_run[r], mx);
            float alpha = __expf(m_run[r] - mn);
            float p0 = __expf(a - mn);
            float p1 = __expf(b - mn);
            float ps = p0 + p1;
            #pragma unroll
            for (int off = 16; off; off >>= 1)
                ps += __shfl_xor_sync(0xffffffffu, ps, off);
            l_run[r] = l_run[r] * alpha + ps;
            m_run[r] = mn;
            o_acc[r][0] *= alpha; o_acc[r][1] *= alpha;
            o_acc[r][2] *= alpha; o_acc[r][3] *= alpha;
            *(float2*)&p_s[m * 64 + cpair] = make_float2(p0, p1);
        }
        __syncwarp();

        // ---- PV: O[r][dbase..+3] += sum_c p[r][c] * v[c][d] ----
        #pragma unroll 4
        for (int cc = 0; cc < 64; cc += 2) {
            float4 v0 = *(const float4*)&v_s[(cc + 0) * 128 + dbase];
            float4 v1 = *(const float4*)&v_s[(cc + 1) * 128 + dbase];
            #pragma unroll
            for (int r = 0; r < 8; r++) {
                float2 p = *(const float2*)&p_s[(rm + r) * 64 + cc];
                o_acc[r][0] += p.x * v0.x + p.y * v1.x;
                o_acc[r][1] += p.x * v0.y + p.y * v1.y;
                o_acc[r][2] += p.x * v0.z + p.y * v1.z;
                o_acc[r][3] += p.x * v0.w + p.y * v1.w;
            }
        }
    }

    // ---- write partials (unnormalized O, running m, l) ----
    size_t pb = (size_t)(kv * NSLICE + slice) * 64;
    #pragma unroll
    for (int r = 0; r < 8; r++) {
        *(float4*)&g_opart[(pb + rm + r) * HD + dbase] =
            make_float4(o_acc[r][0], o_acc[r][1], o_acc[r][2], o_acc[r][3]);
    }
    if (lane == 0) {
        #pragma unroll
        for (int r = 0; r < 8; r++) {
            g_mpart[pb + rm + r] = m_run[r];
            g_lpart[pb + rm + r] = l_run[r];
        }
    }
}

// ---------------- 5. combine split-context partials -------------------------
// grid 512 blocks = (kv, m); 128 threads = d
__global__ void __launch_bounds__(128) combine_kernel() {
    int b  = blockIdx.x;
    int kv = b >> 6;
    int m  = b & 63;
    int d  = threadIdx.x;
    size_t base = (size_t)kv * NSLICE * 64 + m;

    float M = -1e30f;
    #pragma unroll
    for (int s = 0; s < NSLICE; s++)
        M = fmaxf(M, g_mpart[base + s * 64]);
    float num = 0.f, den = 0.f;
    #pragma unroll 4
    for (int s = 0; s < NSLICE; s++) {
        float w = __expf(g_mpart[base + s * 64] - M);
        den += w * g_lpart[base + s * 64];
        num += w * g_opart[(base + s * 64) * HD + d];
    }
    int g = m >> 4, t = m & 15;
    g_o[t * EMBED + (kv * 4 + g) * HD + d] = num / den;
}

// ---------------- launch -----------------------------------------------------
extern "C" void kernel_launch(void* const* d_in, const int* in_sizes, int n_in,
                              void* d_out, int out_size) {
    const float* x      = (const float*)d_in[0];
    const float* norm_w = (const float*)d_in[1];
    const float* wq     = (const float*)d_in[2];
    const float* wk     = (const float*)d_in[3];
    const float* wv     = (const float*)d_in[4];
    const float* wo     = (const float*)d_in[5];
    const float* rc     = (const float*)d_in[6];
    const float* rs     = (const float*)d_in[7];
    const float* ktc    = (const float*)d_in[8];
    const float* vc     = (const float*)d_in[9];
    // d_in[10] = attn_bias (reproduced analytically)
    const float* kq     = (const float*)d_in[11];
    float* out = (float*)d_out;

    const int ATTN_SMEM = (8192 + 8192 + 8192 + 4096) * 4;   // 114688 B
    cudaFuncSetAttribute(attn_kernel,
                         cudaFuncAttributeMaxDynamicSharedMemorySize, ATTN_SMEM);

    rmsnorm_kernel<<<16, 256>>>(x, norm_w);
    qkv_gemm_kernel<<<384, 256>>>(wq, wk, wv);
    rope_kernel<<<dim3(48, 16), 64>>>(rc, rs, kq, out);
    attn_kernel<<<dim3(NKV, NSLICE), 256, ATTN_SMEM>>>(ktc, vc);
    combine_kernel<<<512, 128>>>();
    wo_gemm_kernel<<<256, 256>>>(wo, out);
}